// round 9
// baseline (speedup 1.0000x reference)
#include <cuda_runtime.h>
#include <cstdint>

#define N_GRAPHS 1024
#define N_NODES  65536
#define N_EDGES  262144
#define D        256
#define D_IN     768
#define D_HID    512
#define D_OUT    256

// Scratch (no allocations allowed)
__device__ float g_collected[N_GRAPHS * D_IN];
__device__ float g_hidden[N_GRAPHS * D_HID];

// ---------------------------------------------------------------------------
// Kernel 1: segment sums + concat.
// 8 CTAs per graph; each CTA owns a 32-float (8 x float4) column chunk.
// 256 threads = 32 row-lanes x 8 float4-cols. Sorted ids -> binary search,
// no atomics, deterministic. Warp-shuffle + smem reduction across row lanes.
// Fine granularity (8192 items, ~4.4us each) kills the wave-quantization tail.
// ---------------------------------------------------------------------------
__global__ __launch_bounds__(256) void collect_kernel(
    const float4* __restrict__ nodes,
    const float4* __restrict__ edges,
    const float4* __restrict__ globals_,
    const int* __restrict__ node_ids,
    const int* __restrict__ edge_ids,
    float4* __restrict__ collected4)
{
    const int g     = blockIdx.x >> 3;
    const int chunk = blockIdx.x & 7;     // 8 column chunks of 8 float4
    const int t     = threadIdx.x;
    const int c     = t & 7;              // float4 col within chunk
    const int rl    = t >> 3;             // row lane 0..31
    const int lane  = t & 31;
    const int wid   = t >> 5;
    const int colf4 = chunk * 8 + c;      // 0..63 (row = 64 float4)

    __shared__ int bounds[4];             // [e_lo, e_hi, n_lo, n_hi]
    __shared__ float4 red_e[8][8];        // [warp][col]
    __shared__ float4 red_n[8][8];

    if (t < 4) {
        const int* ids = (t < 2) ? edge_ids : node_ids;
        const int  n   = (t < 2) ? N_EDGES  : N_NODES;
        const int  target = g + (t & 1);
        int lo = 0, hi = n;
        while (lo < hi) {
            int mid = (lo + hi) >> 1;
            if (ids[mid] < target) lo = mid + 1; else hi = mid;
        }
        bounds[t] = lo;
    }
    __syncthreads();

    // Edge accumulation (avg ~8 iters/thread, unrolled for MLP)
    float4 eacc = make_float4(0.f, 0.f, 0.f, 0.f);
    {
        const int lo = bounds[0], hi = bounds[1];
        #pragma unroll 8
        for (int r = lo + rl; r < hi; r += 32) {
            float4 v = __ldcs(&edges[(size_t)r * (D / 4) + colf4]);
            eacc.x += v.x; eacc.y += v.y; eacc.z += v.z; eacc.w += v.w;
        }
    }
    // Node accumulation (avg ~2 iters/thread)
    float4 nacc = make_float4(0.f, 0.f, 0.f, 0.f);
    {
        const int lo = bounds[2], hi = bounds[3];
        #pragma unroll 4
        for (int r = lo + rl; r < hi; r += 32) {
            float4 v = __ldcs(&nodes[(size_t)r * (D / 4) + colf4]);
            nacc.x += v.x; nacc.y += v.y; nacc.z += v.z; nacc.w += v.w;
        }
    }

    // Warp-level reduce across the 4 row-lanes in this warp (lane stride 8,16)
    #pragma unroll
    for (int s = 8; s <= 16; s <<= 1) {
        eacc.x += __shfl_xor_sync(0xffffffffu, eacc.x, s);
        eacc.y += __shfl_xor_sync(0xffffffffu, eacc.y, s);
        eacc.z += __shfl_xor_sync(0xffffffffu, eacc.z, s);
        eacc.w += __shfl_xor_sync(0xffffffffu, eacc.w, s);
        nacc.x += __shfl_xor_sync(0xffffffffu, nacc.x, s);
        nacc.y += __shfl_xor_sync(0xffffffffu, nacc.y, s);
        nacc.z += __shfl_xor_sync(0xffffffffu, nacc.z, s);
        nacc.w += __shfl_xor_sync(0xffffffffu, nacc.w, s);
    }
    if (lane < 8) { red_e[wid][lane] = eacc; red_n[wid][lane] = nacc; }
    __syncthreads();

    // Final cross-warp reduce + stores (row = g*192 float4 in collected)
    if (t < 8) {                       // edge cols [0,256)
        float4 s = red_e[0][t];
        #pragma unroll
        for (int i = 1; i < 8; ++i) {
            float4 v = red_e[i][t];
            s.x += v.x; s.y += v.y; s.z += v.z; s.w += v.w;
        }
        collected4[(size_t)g * (D_IN / 4) + chunk * 8 + t] = s;
    } else if (t < 16) {               // node cols [256,512)
        const int cc = t - 8;
        float4 s = red_n[0][cc];
        #pragma unroll
        for (int i = 1; i < 8; ++i) {
            float4 v = red_n[i][cc];
            s.x += v.x; s.y += v.y; s.z += v.z; s.w += v.w;
        }
        collected4[(size_t)g * (D_IN / 4) + (D / 4) + chunk * 8 + cc] = s;
    } else if (t < 24) {               // globals passthrough [512,768)
        const int cc = t - 16;
        collected4[(size_t)g * (D_IN / 4) + 2 * (D / 4) + chunk * 8 + cc] =
            globals_[(size_t)g * (D / 4) + chunk * 8 + cc];
    }
}

// ---------------------------------------------------------------------------
// Kernel 2: TF32 tensor-core GEMM, C = act(A[M,K] @ B[K,N] + bias)
// CTA tile 64 x (NT*16) x 32, 4 warps (2x2), warp tile 32 x (NT*8),
// mma.sync m16n8k8, fp32 accumulate, register-staged double buffering.
// NT=4 -> BN=64 (GEMM1), NT=2 -> BN=32 (GEMM2, doubles CTA count).
// ---------------------------------------------------------------------------
__device__ __forceinline__ unsigned f2tf32(float x) {
    unsigned r;
    asm("cvt.rna.tf32.f32 %0, %1;" : "=r"(r) : "f"(x));
    return r;
}

__device__ __forceinline__ void mma_tf32(float (&c)[4],
                                         const unsigned (&a)[4],
                                         const unsigned (&b)[2]) {
    asm volatile(
        "mma.sync.aligned.m16n8k8.row.col.f32.tf32.tf32.f32 "
        "{%0,%1,%2,%3}, {%4,%5,%6,%7}, {%8,%9}, {%0,%1,%2,%3};\n"
        : "+f"(c[0]), "+f"(c[1]), "+f"(c[2]), "+f"(c[3])
        : "r"(a[0]), "r"(a[1]), "r"(a[2]), "r"(a[3]),
          "r"(b[0]), "r"(b[1]));
}

template <bool RELU, int NT>
__global__ __launch_bounds__(128) void mma_gemm(
    const float* __restrict__ A,
    const float* __restrict__ B,
    const float* __restrict__ bias,
    float* __restrict__ C,
    int M, int N, int K)
{
    constexpr int BM = 64, BN = NT * 16, BK = 32;
    constexpr int BF4 = BN / 4;            // float4 per B row
    __shared__ unsigned As[BM][BK + 4];    // tf32 bits, [m][k]
    __shared__ unsigned Bs[BK][BN + 4];    // tf32 bits, [k][n]

    const int tid  = threadIdx.x;
    const int wid  = tid >> 5;
    const int lane = tid & 31;
    const int gid  = lane >> 2;
    const int tig  = lane & 3;
    const int m0 = blockIdx.y * BM;
    const int n0 = blockIdx.x * BN;
    const int wm = (wid & 1) * 32;
    const int wn = (wid >> 1) * (NT * 8);

    float4 sa[4], sb[NT];
    float c[2][NT][4];
    #pragma unroll
    for (int i = 0; i < 2; ++i)
        #pragma unroll
        for (int j = 0; j < NT; ++j)
            #pragma unroll
            for (int q = 0; q < 4; ++q) c[i][j][q] = 0.f;

    auto load_tiles = [&](int k0) {
        #pragma unroll
        for (int p = 0; p < 4; ++p) {          // A: 64x32 = 512 f4
            int idx = tid + p * 128;
            int r = idx >> 3, c4 = idx & 7;
            sa[p] = *reinterpret_cast<const float4*>(
                &A[(size_t)(m0 + r) * K + k0 + c4 * 4]);
        }
        #pragma unroll
        for (int p = 0; p < NT; ++p) {         // B: 32xBN = 8*BN f4
            int idx = tid + p * 128;
            int r = idx / BF4, c4 = idx % BF4;
            sb[p] = *reinterpret_cast<const float4*>(
                &B[(size_t)(k0 + r) * N + n0 + c4 * 4]);
        }
    };
    auto store_tiles = [&]() {
        #pragma unroll
        for (int p = 0; p < 4; ++p) {
            int idx = tid + p * 128;
            int r = idx >> 3, c4 = idx & 7;
            uint4 u = make_uint4(f2tf32(sa[p].x), f2tf32(sa[p].y),
                                 f2tf32(sa[p].z), f2tf32(sa[p].w));
            *reinterpret_cast<uint4*>(&As[r][c4 * 4]) = u;
        }
        #pragma unroll
        for (int p = 0; p < NT; ++p) {
            int idx = tid + p * 128;
            int r = idx / BF4, c4 = idx % BF4;
            uint4 u = make_uint4(f2tf32(sb[p].x), f2tf32(sb[p].y),
                                 f2tf32(sb[p].z), f2tf32(sb[p].w));
            *reinterpret_cast<uint4*>(&Bs[r][c4 * 4]) = u;
        }
    };

    load_tiles(0);
    store_tiles();
    __syncthreads();

    for (int k0 = 0; k0 < K; k0 += BK) {
        const bool has_next = (k0 + BK) < K;
        if (has_next) load_tiles(k0 + BK);   // LDG latency overlaps mma

        #pragma unroll
        for (int ks = 0; ks < BK; ks += 8) {
            unsigned a[2][4], b[NT][2];
            #pragma unroll
            for (int mt = 0; mt < 2; ++mt) {
                const int rb = wm + mt * 16 + gid;
                a[mt][0] = As[rb][ks + tig];
                a[mt][1] = As[rb + 8][ks + tig];
                a[mt][2] = As[rb][ks + tig + 4];
                a[mt][3] = As[rb + 8][ks + tig + 4];
            }
            #pragma unroll
            for (int nt = 0; nt < NT; ++nt) {
                const int cb = wn + nt * 8 + gid;
                b[nt][0] = Bs[ks + tig][cb];
                b[nt][1] = Bs[ks + tig + 4][cb];
            }
            #pragma unroll
            for (int mt = 0; mt < 2; ++mt)
                #pragma unroll
                for (int nt = 0; nt < NT; ++nt)
                    mma_tf32(c[mt][nt], a[mt], b[nt]);
        }
        __syncthreads();
        if (has_next) {
            store_tiles();
            __syncthreads();
        }
    }

    // Epilogue: bias (+ReLU)
    #pragma unroll
    for (int mt = 0; mt < 2; ++mt) {
        const int row = m0 + wm + mt * 16 + gid;
        #pragma unroll
        for (int nt = 0; nt < NT; ++nt) {
            const int col = n0 + wn + nt * 8 + 2 * tig;
            float2 bv = *reinterpret_cast<const float2*>(&bias[col]);
            float2 v0, v1;
            v0.x = c[mt][nt][0] + bv.x;
            v0.y = c[mt][nt][1] + bv.y;
            v1.x = c[mt][nt][2] + bv.x;
            v1.y = c[mt][nt][3] + bv.y;
            if (RELU) {
                v0.x = fmaxf(v0.x, 0.f); v0.y = fmaxf(v0.y, 0.f);
                v1.x = fmaxf(v1.x, 0.f); v1.y = fmaxf(v1.y, 0.f);
            }
            *reinterpret_cast<float2*>(&C[(size_t)row * N + col]) = v0;
            *reinterpret_cast<float2*>(&C[(size_t)(row + 8) * N + col]) = v1;
        }
    }
}

extern "C" void kernel_launch(void* const* d_in, const int* in_sizes, int n_in,
                              void* d_out, int out_size)
{
    const float* nodes    = (const float*)d_in[0];
    const float* edges    = (const float*)d_in[1];
    const float* globals_ = (const float*)d_in[2];
    const int*   node_ids = (const int*)d_in[3];
    const int*   edge_ids = (const int*)d_in[4];
    const float* W1       = (const float*)d_in[5];
    const float* b1       = (const float*)d_in[6];
    const float* W2       = (const float*)d_in[7];
    const float* b2       = (const float*)d_in[8];
    float* out = (float*)d_out;

    float* collected = nullptr;
    float* hidden = nullptr;
    cudaGetSymbolAddress((void**)&collected, g_collected);
    cudaGetSymbolAddress((void**)&hidden, g_hidden);

    // Phase 1: segment sums + concat (8 CTAs per graph -> 8192 fine items)
    collect_kernel<<<8 * N_GRAPHS, 256>>>(
        (const float4*)nodes, (const float4*)edges, (const float4*)globals_,
        node_ids, edge_ids, (float4*)collected);

    // Phase 2: hidden = relu(collected @ W1 + b1)   [1024,768]@[768,512]
    {
        dim3 grid(D_HID / 64, N_GRAPHS / 64);       // 8 x 16 = 128 CTAs
        mma_gemm<true, 4><<<grid, 128>>>(collected, W1, b1, hidden,
                                         N_GRAPHS, D_HID, D_IN);
    }
    // Phase 3: out = hidden @ W2 + b2               [1024,512]@[512,256]
    {
        dim3 grid(D_OUT / 32, N_GRAPHS / 64);       // 8 x 16 = 128 CTAs
        mma_gemm<false, 2><<<grid, 128>>>(hidden, W2, b2, out,
                                          N_GRAPHS, D_OUT, D_HID);
    }
}

// round 10
// speedup vs baseline: 1.3720x; 1.3720x over previous
#include <cuda_runtime.h>
#include <cstdint>

#define N_GRAPHS 1024
#define N_NODES  65536
#define N_EDGES  262144
#define D        256
#define D_IN     768
#define D_HID    512
#define D_OUT    256

// Scratch (no allocations allowed)
__device__ float g_collected[N_GRAPHS * D_IN];
__device__ float g_hidden[N_GRAPHS * D_HID];
__device__ int   g_eoff[N_GRAPHS + 1];
__device__ int   g_noff[N_GRAPHS + 1];

// ---------------------------------------------------------------------------
// Kernel 0: one-shot boundary precompute. 2050 parallel binary searches.
// Removes the serial per-CTA search that killed R9.
// ---------------------------------------------------------------------------
__global__ void bounds_kernel(const int* __restrict__ eids,
                              const int* __restrict__ nids)
{
    const int t = blockIdx.x * blockDim.x + threadIdx.x;
    if (t <= N_GRAPHS) {
        int lo = 0, hi = N_EDGES;
        while (lo < hi) {
            int m = (lo + hi) >> 1;
            if (eids[m] < t) lo = m + 1; else hi = m;
        }
        g_eoff[t] = lo;
    } else if (t <= 2 * N_GRAPHS + 1) {
        const int g = t - (N_GRAPHS + 1);
        int lo = 0, hi = N_NODES;
        while (lo < hi) {
            int m = (lo + hi) >> 1;
            if (nids[m] < g) lo = m + 1; else hi = m;
        }
        g_noff[g] = lo;
    }
}

// ---------------------------------------------------------------------------
// Kernel 1: segment sums + concat. 8 CTAs per graph (fine granularity ->
// no wave-quantization tail), bounds read from precomputed offsets.
// 256 threads = 32 row-lanes x 8 float4-cols; each 8-lane group streams one
// full 128B line per row. Warp-shuffle + smem reduce. No atomics.
// ---------------------------------------------------------------------------
__global__ __launch_bounds__(256) void collect_kernel(
    const float4* __restrict__ nodes,
    const float4* __restrict__ edges,
    const float4* __restrict__ globals_,
    float4* __restrict__ collected4)
{
    const int g     = blockIdx.x >> 3;
    const int chunk = blockIdx.x & 7;     // 8 column chunks of 8 float4
    const int t     = threadIdx.x;
    const int c     = t & 7;              // float4 col within chunk
    const int rl    = t >> 3;             // row lane 0..31
    const int lane  = t & 31;
    const int wid   = t >> 5;
    const int colf4 = chunk * 8 + c;      // 0..63

    __shared__ float4 red_e[8][8];        // [warp][col]
    __shared__ float4 red_n[8][8];

    const int elo = __ldg(&g_eoff[g]), ehi = __ldg(&g_eoff[g + 1]);
    const int nlo = __ldg(&g_noff[g]), nhi = __ldg(&g_noff[g + 1]);

    // Edge accumulation (avg ~8 iters/thread, unroll 8 -> MLP 8)
    float4 eacc = make_float4(0.f, 0.f, 0.f, 0.f);
    #pragma unroll 8
    for (int r = elo + rl; r < ehi; r += 32) {
        float4 v = __ldcs(&edges[(size_t)r * (D / 4) + colf4]);
        eacc.x += v.x; eacc.y += v.y; eacc.z += v.z; eacc.w += v.w;
    }
    // Node accumulation (avg ~2 iters/thread)
    float4 nacc = make_float4(0.f, 0.f, 0.f, 0.f);
    #pragma unroll 4
    for (int r = nlo + rl; r < nhi; r += 32) {
        float4 v = __ldcs(&nodes[(size_t)r * (D / 4) + colf4]);
        nacc.x += v.x; nacc.y += v.y; nacc.z += v.z; nacc.w += v.w;
    }

    // Reduce the 4 row-lanes within each warp (lane bit strides 8, 16)
    #pragma unroll
    for (int s = 8; s <= 16; s <<= 1) {
        eacc.x += __shfl_xor_sync(0xffffffffu, eacc.x, s);
        eacc.y += __shfl_xor_sync(0xffffffffu, eacc.y, s);
        eacc.z += __shfl_xor_sync(0xffffffffu, eacc.z, s);
        eacc.w += __shfl_xor_sync(0xffffffffu, eacc.w, s);
        nacc.x += __shfl_xor_sync(0xffffffffu, nacc.x, s);
        nacc.y += __shfl_xor_sync(0xffffffffu, nacc.y, s);
        nacc.z += __shfl_xor_sync(0xffffffffu, nacc.z, s);
        nacc.w += __shfl_xor_sync(0xffffffffu, nacc.w, s);
    }
    if (lane < 8) { red_e[wid][lane] = eacc; red_n[wid][lane] = nacc; }
    __syncthreads();

    // Final cross-warp reduce + stores (row = g * 192 float4)
    if (t < 8) {                       // edge cols [0,256)
        float4 s = red_e[0][t];
        #pragma unroll
        for (int i = 1; i < 8; ++i) {
            float4 v = red_e[i][t];
            s.x += v.x; s.y += v.y; s.z += v.z; s.w += v.w;
        }
        collected4[(size_t)g * (D_IN / 4) + chunk * 8 + t] = s;
    } else if (t < 16) {               // node cols [256,512)
        const int cc = t - 8;
        float4 s = red_n[0][cc];
        #pragma unroll
        for (int i = 1; i < 8; ++i) {
            float4 v = red_n[i][cc];
            s.x += v.x; s.y += v.y; s.z += v.z; s.w += v.w;
        }
        collected4[(size_t)g * (D_IN / 4) + (D / 4) + chunk * 8 + cc] = s;
    } else if (t < 24) {               // globals passthrough [512,768)
        const int cc = t - 16;
        collected4[(size_t)g * (D_IN / 4) + 2 * (D / 4) + chunk * 8 + cc] =
            globals_[(size_t)g * (D / 4) + chunk * 8 + cc];
    }
}

// ---------------------------------------------------------------------------
// Kernel 2: TF32 tensor-core GEMM, C = act(A[M,K] @ B[K,N] + bias)
// CTA tile 64 x (NT*16) x 32, 4 warps (2x2), mma.sync m16n8k8, fp32 acc,
// register-staged double buffering. NT=2 -> BN=32 (more CTAs, better SM fill).
// ---------------------------------------------------------------------------
__device__ __forceinline__ unsigned f2tf32(float x) {
    unsigned r;
    asm("cvt.rna.tf32.f32 %0, %1;" : "=r"(r) : "f"(x));
    return r;
}

__device__ __forceinline__ void mma_tf32(float (&c)[4],
                                         const unsigned (&a)[4],
                                         const unsigned (&b)[2]) {
    asm volatile(
        "mma.sync.aligned.m16n8k8.row.col.f32.tf32.tf32.f32 "
        "{%0,%1,%2,%3}, {%4,%5,%6,%7}, {%8,%9}, {%0,%1,%2,%3};\n"
        : "+f"(c[0]), "+f"(c[1]), "+f"(c[2]), "+f"(c[3])
        : "r"(a[0]), "r"(a[1]), "r"(a[2]), "r"(a[3]),
          "r"(b[0]), "r"(b[1]));
}

template <bool RELU, int NT>
__global__ __launch_bounds__(128) void mma_gemm(
    const float* __restrict__ A,
    const float* __restrict__ B,
    const float* __restrict__ bias,
    float* __restrict__ C,
    int M, int N, int K)
{
    constexpr int BM = 64, BN = NT * 16, BK = 32;
    constexpr int BF4 = BN / 4;
    __shared__ unsigned As[BM][BK + 4];
    __shared__ unsigned Bs[BK][BN + 4];

    const int tid  = threadIdx.x;
    const int wid  = tid >> 5;
    const int lane = tid & 31;
    const int gid  = lane >> 2;
    const int tig  = lane & 3;
    const int m0 = blockIdx.y * BM;
    const int n0 = blockIdx.x * BN;
    const int wm = (wid & 1) * 32;
    const int wn = (wid >> 1) * (NT * 8);

    float4 sa[4], sb[NT];
    float c[2][NT][4];
    #pragma unroll
    for (int i = 0; i < 2; ++i)
        #pragma unroll
        for (int j = 0; j < NT; ++j)
            #pragma unroll
            for (int q = 0; q < 4; ++q) c[i][j][q] = 0.f;

    auto load_tiles = [&](int k0) {
        #pragma unroll
        for (int p = 0; p < 4; ++p) {
            int idx = tid + p * 128;
            int r = idx >> 3, c4 = idx & 7;
            sa[p] = *reinterpret_cast<const float4*>(
                &A[(size_t)(m0 + r) * K + k0 + c4 * 4]);
        }
        #pragma unroll
        for (int p = 0; p < NT; ++p) {
            int idx = tid + p * 128;
            int r = idx / BF4, c4 = idx % BF4;
            sb[p] = *reinterpret_cast<const float4*>(
                &B[(size_t)(k0 + r) * N + n0 + c4 * 4]);
        }
    };
    auto store_tiles = [&]() {
        #pragma unroll
        for (int p = 0; p < 4; ++p) {
            int idx = tid + p * 128;
            int r = idx >> 3, c4 = idx & 7;
            uint4 u = make_uint4(f2tf32(sa[p].x), f2tf32(sa[p].y),
                                 f2tf32(sa[p].z), f2tf32(sa[p].w));
            *reinterpret_cast<uint4*>(&As[r][c4 * 4]) = u;
        }
        #pragma unroll
        for (int p = 0; p < NT; ++p) {
            int idx = tid + p * 128;
            int r = idx / BF4, c4 = idx % BF4;
            uint4 u = make_uint4(f2tf32(sb[p].x), f2tf32(sb[p].y),
                                 f2tf32(sb[p].z), f2tf32(sb[p].w));
            *reinterpret_cast<uint4*>(&Bs[r][c4 * 4]) = u;
        }
    };

    load_tiles(0);
    store_tiles();
    __syncthreads();

    for (int k0 = 0; k0 < K; k0 += BK) {
        const bool has_next = (k0 + BK) < K;
        if (has_next) load_tiles(k0 + BK);   // LDG latency overlaps mma

        #pragma unroll
        for (int ks = 0; ks < BK; ks += 8) {
            unsigned a[2][4], b[NT][2];
            #pragma unroll
            for (int mt = 0; mt < 2; ++mt) {
                const int rb = wm + mt * 16 + gid;
                a[mt][0] = As[rb][ks + tig];
                a[mt][1] = As[rb + 8][ks + tig];
                a[mt][2] = As[rb][ks + tig + 4];
                a[mt][3] = As[rb + 8][ks + tig + 4];
            }
            #pragma unroll
            for (int nt = 0; nt < NT; ++nt) {
                const int cb = wn + nt * 8 + gid;
                b[nt][0] = Bs[ks + tig][cb];
                b[nt][1] = Bs[ks + tig + 4][cb];
            }
            #pragma unroll
            for (int mt = 0; mt < 2; ++mt)
                #pragma unroll
                for (int nt = 0; nt < NT; ++nt)
                    mma_tf32(c[mt][nt], a[mt], b[nt]);
        }
        __syncthreads();
        if (has_next) {
            store_tiles();
            __syncthreads();
        }
    }

    // Epilogue: bias (+ReLU)
    #pragma unroll
    for (int mt = 0; mt < 2; ++mt) {
        const int row = m0 + wm + mt * 16 + gid;
        #pragma unroll
        for (int nt = 0; nt < NT; ++nt) {
            const int col = n0 + wn + nt * 8 + 2 * tig;
            float2 bv = *reinterpret_cast<const float2*>(&bias[col]);
            float2 v0, v1;
            v0.x = c[mt][nt][0] + bv.x;
            v0.y = c[mt][nt][1] + bv.y;
            v1.x = c[mt][nt][2] + bv.x;
            v1.y = c[mt][nt][3] + bv.y;
            if (RELU) {
                v0.x = fmaxf(v0.x, 0.f); v0.y = fmaxf(v0.y, 0.f);
                v1.x = fmaxf(v1.x, 0.f); v1.y = fmaxf(v1.y, 0.f);
            }
            *reinterpret_cast<float2*>(&C[(size_t)row * N + col]) = v0;
            *reinterpret_cast<float2*>(&C[(size_t)(row + 8) * N + col]) = v1;
        }
    }
}

extern "C" void kernel_launch(void* const* d_in, const int* in_sizes, int n_in,
                              void* d_out, int out_size)
{
    const float* nodes    = (const float*)d_in[0];
    const float* edges    = (const float*)d_in[1];
    const float* globals_ = (const float*)d_in[2];
    const int*   node_ids = (const int*)d_in[3];
    const int*   edge_ids = (const int*)d_in[4];
    const float* W1       = (const float*)d_in[5];
    const float* b1       = (const float*)d_in[6];
    const float* W2       = (const float*)d_in[7];
    const float* b2       = (const float*)d_in[8];
    float* out = (float*)d_out;

    float* collected = nullptr;
    float* hidden = nullptr;
    cudaGetSymbolAddress((void**)&collected, g_collected);
    cudaGetSymbolAddress((void**)&hidden, g_hidden);

    // Phase 0: all segment boundaries, once (2050 parallel searches)
    bounds_kernel<<<(2 * (N_GRAPHS + 1) + 255) / 256, 256>>>(edge_ids, node_ids);

    // Phase 1: segment sums + concat (8 fine CTAs per graph, no search)
    collect_kernel<<<8 * N_GRAPHS, 256>>>(
        (const float4*)nodes, (const float4*)edges, (const float4*)globals_,
        (float4*)collected);

    // Phase 2: hidden = relu(collected @ W1 + b1)   [1024,768]@[768,512]
    {
        dim3 grid(D_HID / 32, N_GRAPHS / 64);       // 16 x 16 = 256 CTAs
        mma_gemm<true, 2><<<grid, 128>>>(collected, W1, b1, hidden,
                                         N_GRAPHS, D_HID, D_IN);
    }
    // Phase 3: out = hidden @ W2 + b2               [1024,512]@[512,256]
    {
        dim3 grid(D_OUT / 32, N_GRAPHS / 64);       // 8 x 16 = 128 CTAs
        mma_gemm<false, 2><<<grid, 128>>>(hidden, W2, b2, out,
                                          N_GRAPHS, D_OUT, D_HID);
    }
}